// round 1
// baseline (speedup 1.0000x reference)
#include <cuda_runtime.h>
#include <math.h>

#define NPTS 1024
#define TPB  256
#define MAXB 8192

// Scratch for per-batch TM partial sums (no cudaMalloc allowed).
__device__ float g_partial[MAXB];

__device__ __forceinline__ float warp_sum(float v) {
#pragma unroll
    for (int o = 16; o; o >>= 1) v += __shfl_xor_sync(0xffffffffu, v, o);
    return v;
}

// One cyclic-Jacobi rotation zeroing A[P][Q] of a symmetric 3x3; V accumulates
// the right eigenvector basis (B = V Lambda V^T).
template <int P, int Q>
__device__ __forceinline__ void jacobi_rot(float A[3][3], float V[3][3]) {
    float apq = A[P][Q];
    if (fabsf(apq) < 1e-20f) return;
    float tau = (A[Q][Q] - A[P][P]) / (2.0f * apq);
    float t = ((tau >= 0.f) ? 1.f : -1.f) / (fabsf(tau) + sqrtf(1.f + tau * tau));
    float c = rsqrtf(1.f + t * t);
    float s = t * c;
#pragma unroll
    for (int r = 0; r < 3; r++) {
        float arp = A[r][P], arq = A[r][Q];
        A[r][P] = c * arp - s * arq;
        A[r][Q] = s * arp + c * arq;
    }
#pragma unroll
    for (int cc = 0; cc < 3; cc++) {
        float apc = A[P][cc], aqc = A[Q][cc];
        A[P][cc] = c * apc - s * aqc;
        A[Q][cc] = s * apc + c * aqc;
    }
#pragma unroll
    for (int r = 0; r < 3; r++) {
        float vrp = V[r][P], vrq = V[r][Q];
        V[r][P] = c * vrp - s * vrq;
        V[r][Q] = s * vrp + c * vrq;
    }
}

__global__ __launch_bounds__(TPB) void tm_kernel(const float* __restrict__ pred,
                                                 const float* __restrict__ act,
                                                 float d0sq) {
    __shared__ float sp[3 * NPTS];
    __shared__ float sq[3 * NPTS];
    __shared__ float red[8][16];   // 8 warps x 15 partials (padded)
    __shared__ float sRm[16];      // R[9], mu_p[3], mu_q[3]

    const int b = blockIdx.x;
    const int tid = threadIdx.x;
    const int wid = tid >> 5;
    const int lane = tid & 31;

    // ---- Stage both coordinate sets into SMEM (single DRAM read) ----
    const float4* p4 = (const float4*)(pred + (size_t)b * 3 * NPTS);
    const float4* q4 = (const float4*)(act + (size_t)b * 3 * NPTS);
    float4* sp4 = (float4*)sp;
    float4* sq4 = (float4*)sq;
#pragma unroll
    for (int i = tid; i < (3 * NPTS) / 4; i += TPB) {
        sp4[i] = p4[i];
        sq4[i] = q4[i];
    }
    __syncthreads();

    // ---- Phase 1: sums + raw cross-products ----
    float acc[15];
#pragma unroll
    for (int v = 0; v < 15; v++) acc[v] = 0.f;

    for (int k = tid; k < NPTS; k += TPB) {
        float px = sp[3 * k + 0], py = sp[3 * k + 1], pz = sp[3 * k + 2];
        float qx = sq[3 * k + 0], qy = sq[3 * k + 1], qz = sq[3 * k + 2];
        acc[0] += px;  acc[1] += py;  acc[2] += pz;
        acc[3] += qx;  acc[4] += qy;  acc[5] += qz;
        acc[6] += qx * px;  acc[7] += qx * py;  acc[8] += qx * pz;
        acc[9] += qy * px;  acc[10] += qy * py; acc[11] += qy * pz;
        acc[12] += qz * px; acc[13] += qz * py; acc[14] += qz * pz;
    }
#pragma unroll
    for (int v = 0; v < 15; v++) {
        float r = warp_sum(acc[v]);
        if (lane == 0) red[wid][v] = r;
    }
    __syncthreads();

    // ---- Thread 0: Kabsch rotation (3x3 SVD via Jacobi on M^T M) ----
    if (tid == 0) {
        float tot[15];
#pragma unroll
        for (int v = 0; v < 15; v++) {
            float t = 0.f;
#pragma unroll
            for (int w = 0; w < TPB / 32; w++) t += red[w][v];
            tot[v] = t;
        }
        const float inv_n = 1.0f / (float)NPTS;
        float mup[3] = {tot[0] * inv_n, tot[1] * inv_n, tot[2] * inv_n};
        float muq[3] = {tot[3] * inv_n, tot[4] * inv_n, tot[5] * inv_n};

        // Centered cross-covariance M[i][j] = sum_n q_i p_j - n*muq_i*mup_j
        float M[3][3];
#pragma unroll
        for (int i = 0; i < 3; i++)
#pragma unroll
            for (int j = 0; j < 3; j++)
                M[i][j] = tot[6 + 3 * i + j] - (float)NPTS * muq[i] * mup[j];

        // Normalize for conditioning (R is scale-invariant).
        float sc = 1e-30f;
#pragma unroll
        for (int i = 0; i < 3; i++)
#pragma unroll
            for (int j = 0; j < 3; j++) sc = fmaxf(sc, fabsf(M[i][j]));
        float invsc = 1.0f / sc;
        float a[3][3];
#pragma unroll
        for (int i = 0; i < 3; i++)
#pragma unroll
            for (int j = 0; j < 3; j++) a[i][j] = M[i][j] * invsc;

        // B = a^T a (symmetric)
        float A[3][3];
#pragma unroll
        for (int i = 0; i < 3; i++)
#pragma unroll
            for (int j = 0; j < 3; j++) {
                float s = 0.f;
#pragma unroll
                for (int k = 0; k < 3; k++) s += a[k][i] * a[k][j];
                A[i][j] = s;
            }
        float V[3][3] = {{1.f, 0.f, 0.f}, {0.f, 1.f, 0.f}, {0.f, 0.f, 1.f}};
#pragma unroll
        for (int sweep = 0; sweep < 8; sweep++) {
            jacobi_rot<0, 1>(A, V);
            jacobi_rot<0, 2>(A, V);
            jacobi_rot<1, 2>(A, V);
        }
        float lam[3] = {A[0][0], A[1][1], A[2][2]};
        int imin = (lam[0] < lam[1]) ? ((lam[0] < lam[2]) ? 0 : 2)
                                     : ((lam[1] < lam[2]) ? 1 : 2);
        // d = sign(det U * det Vt) = sign(det M) (singular values >= 0)
        float det = a[0][0] * (a[1][1] * a[2][2] - a[1][2] * a[2][1]) -
                    a[0][1] * (a[1][0] * a[2][2] - a[1][2] * a[2][0]) +
                    a[0][2] * (a[1][0] * a[2][1] - a[1][1] * a[2][0]);
        float dsgn = (det >= 0.f) ? 1.f : -1.f;
        float cvec[3];
#pragma unroll
        for (int k = 0; k < 3; k++) {
            float s_ = sqrtf(fmaxf(lam[k], 1e-30f));
            cvec[k] = ((k == imin) ? dsgn : 1.f) / s_;
        }
        // G = V diag(cvec) V^T ;  R = a * G  (scale cancels)
        float G[3][3];
#pragma unroll
        for (int i = 0; i < 3; i++)
#pragma unroll
            for (int j = 0; j < 3; j++) {
                float s = 0.f;
#pragma unroll
                for (int k = 0; k < 3; k++) s += cvec[k] * V[i][k] * V[j][k];
                G[i][j] = s;
            }
#pragma unroll
        for (int i = 0; i < 3; i++)
#pragma unroll
            for (int j = 0; j < 3; j++) {
                float s = 0.f;
#pragma unroll
                for (int k = 0; k < 3; k++) s += a[i][k] * G[k][j];
                sRm[3 * i + j] = s;
            }
        sRm[9] = mup[0];  sRm[10] = mup[1]; sRm[11] = mup[2];
        sRm[12] = muq[0]; sRm[13] = muq[1]; sRm[14] = muq[2];
    }
    __syncthreads();

    // ---- Phase 2: per-residue deviation + TM term (all from SMEM) ----
    const float R00 = sRm[0], R01 = sRm[1], R02 = sRm[2];
    const float R10 = sRm[3], R11 = sRm[4], R12 = sRm[5];
    const float R20 = sRm[6], R21 = sRm[7], R22 = sRm[8];
    const float mup0 = sRm[9], mup1 = sRm[10], mup2 = sRm[11];
    const float muq0 = sRm[12], muq1 = sRm[13], muq2 = sRm[14];
    const float EPS = 1e-8f;

    float fsum = 0.f;
    for (int k = tid; k < NPTS; k += TPB) {
        float qx = sq[3 * k + 0] - muq0;
        float qy = sq[3 * k + 1] - muq1;
        float qz = sq[3 * k + 2] - muq2;
        // aligned_j = sum_i qc_i * R[i][j]   (row-vector @ R)
        float ax = qx * R00 + qy * R10 + qz * R20;
        float ay = qx * R01 + qy * R11 + qz * R21;
        float az = qx * R02 + qy * R12 + qz * R22;
        float dx = (sp[3 * k + 0] - mup0) - ax + EPS;
        float dy = (sp[3 * k + 1] - mup1) - ay + EPS;
        float dz = (sp[3 * k + 2] - mup2) - az + EPS;
        float d2 = dx * dx + dy * dy + dz * dz;
        fsum += d0sq / (d0sq + d2);  // == 1/(1+(dev/d0)^2), no sqrt needed
    }
    fsum = warp_sum(fsum);
    if (lane == 0) red[wid][0] = fsum;
    __syncthreads();
    if (tid == 0) {
        float t = 0.f;
#pragma unroll
        for (int w = 0; w < TPB / 32; w++) t += red[w][0];
        g_partial[b] = t;
    }
}

__global__ void final_kernel(float* __restrict__ out, int b, float scale) {
    __shared__ float sh[32];
    int tid = threadIdx.x;
    float v = 0.f;
    for (int i = tid; i < b; i += blockDim.x) v += g_partial[i];
    v = warp_sum(v);
    if ((tid & 31) == 0) sh[tid >> 5] = v;
    __syncthreads();
    if (tid < 32) {
        float w = (tid < (int)(blockDim.x >> 5)) ? sh[tid] : 0.f;
        w = warp_sum(w);
        if (tid == 0) out[0] = -w * scale;
    }
}

extern "C" void kernel_launch(void* const* d_in, const int* in_sizes, int n_in,
                              void* d_out, int out_size) {
    const float* pred = (const float*)d_in[0];
    const float* act = (const float*)d_in[1];
    float* out = (float*)d_out;

    int b = in_sizes[0] / (3 * NPTS);
    if (b > MAXB) b = MAXB;

    // d0 = 1.24*(n-15)^(1/3) - 1.8, n = NPTS
    double d0 = 1.24 * cbrt((double)NPTS - 15.0) - 1.8;
    float d0sq = (float)(d0 * d0);
    float scale = 1.0f / ((float)b * (float)NPTS);

    tm_kernel<<<b, TPB>>>(pred, act, d0sq);
    final_kernel<<<1, 1024>>>(out, b, scale);
}

// round 2
// speedup vs baseline: 1.0756x; 1.0756x over previous
#include <cuda_runtime.h>
#include <math.h>

#define NPTS 1024
#define TPB  256
#define PPT  4            // points per thread (NPTS / TPB)
#define MAXB 8192

__device__ float g_partial[MAXB];
__device__ unsigned g_count = 0;

__device__ __forceinline__ float warp_sum(float v) {
#pragma unroll
    for (int o = 16; o; o >>= 1) v += __shfl_xor_sync(0xffffffffu, v, o);
    return v;
}

template <int P, int Q>
__device__ __forceinline__ void jacobi_rot(float A[3][3], float V[3][3]) {
    float apq = A[P][Q];
    if (fabsf(apq) < 1e-20f) return;
    float tau = __fdividef(A[Q][Q] - A[P][P], 2.0f * apq);
    float t = __fdividef((tau >= 0.f) ? 1.f : -1.f,
                         fabsf(tau) + sqrtf(1.f + tau * tau));
    float c = rsqrtf(1.f + t * t);
    float s = t * c;
#pragma unroll
    for (int r = 0; r < 3; r++) {
        float arp = A[r][P], arq = A[r][Q];
        A[r][P] = c * arp - s * arq;
        A[r][Q] = s * arp + c * arq;
    }
#pragma unroll
    for (int cc = 0; cc < 3; cc++) {
        float apc = A[P][cc], aqc = A[Q][cc];
        A[P][cc] = c * apc - s * aqc;
        A[Q][cc] = s * apc + c * aqc;
    }
#pragma unroll
    for (int r = 0; r < 3; r++) {
        float vrp = V[r][P], vrq = V[r][Q];
        V[r][P] = c * vrp - s * vrq;
        V[r][Q] = s * vrp + c * vrq;
    }
}

__global__ __launch_bounds__(TPB) void tm_kernel(const float* __restrict__ pred,
                                                 const float* __restrict__ act,
                                                 float d0sq,
                                                 float* __restrict__ out,
                                                 float scale) {
    __shared__ float sp[3 * NPTS];
    __shared__ float sq[3 * NPTS];
    __shared__ float red[8][16];
    __shared__ float sRm[16];
    __shared__ int s_last;

    const int b = blockIdx.x;
    const int tid = threadIdx.x;
    const int wid = tid >> 5;
    const int lane = tid & 31;

    // ---- Load 3 float4s per tensor per thread = 4 whole points each ----
    const float4* p4 = (const float4*)(pred + (size_t)b * 3 * NPTS);
    const float4* q4 = (const float4*)(act + (size_t)b * 3 * NPTS);
    float4* sp4 = (float4*)sp;
    float4* sq4 = (float4*)sq;

    float4 pa = p4[3 * tid + 0], pb = p4[3 * tid + 1], pc = p4[3 * tid + 2];
    float4 qa = q4[3 * tid + 0], qb = q4[3 * tid + 1], qc = q4[3 * tid + 2];
    sp4[3 * tid + 0] = pa; sp4[3 * tid + 1] = pb; sp4[3 * tid + 2] = pc;
    sq4[3 * tid + 0] = qa; sq4[3 * tid + 1] = qb; sq4[3 * tid + 2] = qc;

    // Unpack 4 points, accumulate phase-1 sums directly from registers.
    float px[PPT] = {pa.x, pa.w, pb.z, pc.y};
    float py[PPT] = {pa.y, pb.x, pb.w, pc.z};
    float pz[PPT] = {pa.z, pb.y, pc.x, pc.w};
    float qx[PPT] = {qa.x, qa.w, qb.z, qc.y};
    float qy[PPT] = {qa.y, qb.x, qb.w, qc.z};
    float qz[PPT] = {qa.z, qb.y, qc.x, qc.w};

    float acc[15];
#pragma unroll
    for (int v = 0; v < 15; v++) acc[v] = 0.f;
#pragma unroll
    for (int k = 0; k < PPT; k++) {
        acc[0] += px[k]; acc[1] += py[k]; acc[2] += pz[k];
        acc[3] += qx[k]; acc[4] += qy[k]; acc[5] += qz[k];
        acc[6] += qx[k] * px[k]; acc[7] += qx[k] * py[k]; acc[8] += qx[k] * pz[k];
        acc[9] += qy[k] * px[k]; acc[10] += qy[k] * py[k]; acc[11] += qy[k] * pz[k];
        acc[12] += qz[k] * px[k]; acc[13] += qz[k] * py[k]; acc[14] += qz[k] * pz[k];
    }
#pragma unroll
    for (int v = 0; v < 15; v++) {
        float r = warp_sum(acc[v]);
        if (lane == 0) red[wid][v] = r;
    }
    __syncthreads();

    // ---- Thread 0: Kabsch rotation via Jacobi on M^T M ----
    if (tid == 0) {
        float tot[15];
#pragma unroll
        for (int v = 0; v < 15; v++) {
            float t = 0.f;
#pragma unroll
            for (int w = 0; w < TPB / 32; w++) t += red[w][v];
            tot[v] = t;
        }
        const float inv_n = 1.0f / (float)NPTS;
        float mup[3] = {tot[0] * inv_n, tot[1] * inv_n, tot[2] * inv_n};
        float muq[3] = {tot[3] * inv_n, tot[4] * inv_n, tot[5] * inv_n};

        float M[3][3];
#pragma unroll
        for (int i = 0; i < 3; i++)
#pragma unroll
            for (int j = 0; j < 3; j++)
                M[i][j] = tot[6 + 3 * i + j] - (float)NPTS * muq[i] * mup[j];

        float sc = 1e-30f;
#pragma unroll
        for (int i = 0; i < 3; i++)
#pragma unroll
            for (int j = 0; j < 3; j++) sc = fmaxf(sc, fabsf(M[i][j]));
        float invsc = __fdividef(1.0f, sc);
        float a[3][3];
#pragma unroll
        for (int i = 0; i < 3; i++)
#pragma unroll
            for (int j = 0; j < 3; j++) a[i][j] = M[i][j] * invsc;

        float A[3][3];
#pragma unroll
        for (int i = 0; i < 3; i++)
#pragma unroll
            for (int j = 0; j < 3; j++) {
                float s = 0.f;
#pragma unroll
                for (int k = 0; k < 3; k++) s += a[k][i] * a[k][j];
                A[i][j] = s;
            }
        float V[3][3] = {{1.f, 0.f, 0.f}, {0.f, 1.f, 0.f}, {0.f, 0.f, 1.f}};
#pragma unroll
        for (int sweep = 0; sweep < 6; sweep++) {
            jacobi_rot<0, 1>(A, V);
            jacobi_rot<0, 2>(A, V);
            jacobi_rot<1, 2>(A, V);
        }
        float lam[3] = {A[0][0], A[1][1], A[2][2]};
        int imin = (lam[0] < lam[1]) ? ((lam[0] < lam[2]) ? 0 : 2)
                                     : ((lam[1] < lam[2]) ? 1 : 2);
        float det = a[0][0] * (a[1][1] * a[2][2] - a[1][2] * a[2][1]) -
                    a[0][1] * (a[1][0] * a[2][2] - a[1][2] * a[2][0]) +
                    a[0][2] * (a[1][0] * a[2][1] - a[1][1] * a[2][0]);
        float dsgn = (det >= 0.f) ? 1.f : -1.f;
        float cvec[3];
#pragma unroll
        for (int k = 0; k < 3; k++) {
            float s_ = sqrtf(fmaxf(lam[k], 1e-30f));
            cvec[k] = __fdividef((k == imin) ? dsgn : 1.f, s_);
        }
        float G[3][3];
#pragma unroll
        for (int i = 0; i < 3; i++)
#pragma unroll
            for (int j = 0; j < 3; j++) {
                float s = 0.f;
#pragma unroll
                for (int k = 0; k < 3; k++) s += cvec[k] * V[i][k] * V[j][k];
                G[i][j] = s;
            }
#pragma unroll
        for (int i = 0; i < 3; i++)
#pragma unroll
            for (int j = 0; j < 3; j++) {
                float s = 0.f;
#pragma unroll
                for (int k = 0; k < 3; k++) s += a[i][k] * G[k][j];
                sRm[3 * i + j] = s;
            }
        sRm[9] = mup[0];  sRm[10] = mup[1]; sRm[11] = mup[2];
        sRm[12] = muq[0]; sRm[13] = muq[1]; sRm[14] = muq[2];
    }
    __syncthreads();

    // ---- Phase 2: per-residue deviation + TM term from SMEM ----
    const float R00 = sRm[0], R01 = sRm[1], R02 = sRm[2];
    const float R10 = sRm[3], R11 = sRm[4], R12 = sRm[5];
    const float R20 = sRm[6], R21 = sRm[7], R22 = sRm[8];
    const float mup0 = sRm[9], mup1 = sRm[10], mup2 = sRm[11];
    const float muq0 = sRm[12], muq1 = sRm[13], muq2 = sRm[14];
    const float EPS = 1e-8f;

    float4 ra = sp4[3 * tid + 0], rb = sp4[3 * tid + 1], rc = sp4[3 * tid + 2];
    float4 sa = sq4[3 * tid + 0], sb = sq4[3 * tid + 1], scq = sq4[3 * tid + 2];
    float ppx[PPT] = {ra.x, ra.w, rb.z, rc.y};
    float ppy[PPT] = {ra.y, rb.x, rb.w, rc.z};
    float ppz[PPT] = {ra.z, rb.y, rc.x, rc.w};
    float qqx[PPT] = {sa.x, sa.w, sb.z, scq.y};
    float qqy[PPT] = {sa.y, sb.x, sb.w, scq.z};
    float qqz[PPT] = {sa.z, sb.y, scq.x, scq.w};

    float fsum = 0.f;
#pragma unroll
    for (int k = 0; k < PPT; k++) {
        float cx = qqx[k] - muq0;
        float cy = qqy[k] - muq1;
        float cz = qqz[k] - muq2;
        float ax = cx * R00 + cy * R10 + cz * R20;
        float ay = cx * R01 + cy * R11 + cz * R21;
        float az = cx * R02 + cy * R12 + cz * R22;
        float dx = (ppx[k] - mup0) - ax + EPS;
        float dy = (ppy[k] - mup1) - ay + EPS;
        float dz = (ppz[k] - mup2) - az + EPS;
        float d2 = dx * dx + dy * dy + dz * dz;
        fsum += d0sq / (d0sq + d2);
    }
    fsum = warp_sum(fsum);
    if (lane == 0) red[wid][0] = fsum;
    __syncthreads();

    // ---- Per-batch partial + fused deterministic final reduction ----
    if (tid == 0) {
        float t = 0.f;
#pragma unroll
        for (int w = 0; w < TPB / 32; w++) t += red[w][0];
        g_partial[b] = t;
        __threadfence();
        unsigned r = atomicAdd(&g_count, 1u);
        s_last = (r == gridDim.x - 1) ? 1 : 0;
    }
    __syncthreads();

    if (s_last) {
        const int nb = gridDim.x;
        float v = 0.f;
        for (int i = tid; i < nb; i += TPB) v += __ldcg(&g_partial[i]);
        v = warp_sum(v);
        if (lane == 0) red[wid][1] = v;
        __syncthreads();
        if (tid == 0) {
            float t = 0.f;
#pragma unroll
            for (int w = 0; w < TPB / 32; w++) t += red[w][1];
            out[0] = -t * scale;
            g_count = 0;  // reset for next replay (determinism)
        }
    }
}

extern "C" void kernel_launch(void* const* d_in, const int* in_sizes, int n_in,
                              void* d_out, int out_size) {
    const float* pred = (const float*)d_in[0];
    const float* act = (const float*)d_in[1];
    float* out = (float*)d_out;

    int b = in_sizes[0] / (3 * NPTS);
    if (b > MAXB) b = MAXB;

    double d0 = 1.24 * cbrt((double)NPTS - 15.0) - 1.8;
    float d0sq = (float)(d0 * d0);
    float scale = 1.0f / ((float)b * (float)NPTS);

    tm_kernel<<<b, TPB>>>(pred, act, d0sq, out, scale);
}

// round 3
// speedup vs baseline: 1.3908x; 1.2931x over previous
#include <cuda_runtime.h>
#include <math.h>

#define NPTS 1024
#define TPB  256
#define PPT  4
#define MAXB 8192

__device__ float g_partial[MAXB];
__device__ unsigned g_count = 0;

__device__ __forceinline__ float warp_sum(float v) {
#pragma unroll
    for (int o = 16; o; o >>= 1) v += __shfl_xor_sync(0xffffffffu, v, o);
    return v;
}

// Eigenvector of symmetric B for eigenvalue lam via best cross-product of
// rows of (B - lam*I). Valid for simple (non-repeated) eigenvalues.
__device__ __forceinline__ void eigvec3(const float B[3][3], float lam, float v[3]) {
    float r0x = B[0][0] - lam, r0y = B[0][1],        r0z = B[0][2];
    float r1x = B[0][1],        r1y = B[1][1] - lam, r1z = B[1][2];
    float r2x = B[0][2],        r2y = B[1][2],        r2z = B[2][2] - lam;

    float c0x = r0y * r1z - r0z * r1y, c0y = r0z * r1x - r0x * r1z, c0z = r0x * r1y - r0y * r1x;
    float c1x = r0y * r2z - r0z * r2y, c1y = r0z * r2x - r0x * r2z, c1z = r0x * r2y - r0y * r2x;
    float c2x = r1y * r2z - r1z * r2y, c2y = r1z * r2x - r1x * r2z, c2z = r1x * r2y - r1y * r2x;

    float n0 = c0x * c0x + c0y * c0y + c0z * c0z;
    float n1 = c1x * c1x + c1y * c1y + c1z * c1z;
    float n2 = c2x * c2x + c2y * c2y + c2z * c2z;

    float bx = c0x, by = c0y, bz = c0z, bn = n0;
    if (n1 > bn) { bx = c1x; by = c1y; bz = c1z; bn = n1; }
    if (n2 > bn) { bx = c2x; by = c2y; bz = c2z; bn = n2; }
    float inv = rsqrtf(fmaxf(bn, 1e-30f));
    v[0] = bx * inv; v[1] = by * inv; v[2] = bz * inv;
}

__global__ __launch_bounds__(TPB) void tm_kernel(const float* __restrict__ pred,
                                                 const float* __restrict__ act,
                                                 float d0sq,
                                                 float* __restrict__ out,
                                                 float scale) {
    __shared__ float sp[3 * NPTS];
    __shared__ float sq[3 * NPTS];
    __shared__ float red[8][16];
    __shared__ float sRm[16];
    __shared__ int s_last;

    const int b = blockIdx.x;
    const int tid = threadIdx.x;
    const int wid = tid >> 5;
    const int lane = tid & 31;

    // ---- Load 3 float4s per tensor per thread = 4 whole points each ----
    const float4* p4 = (const float4*)(pred + (size_t)b * 3 * NPTS);
    const float4* q4 = (const float4*)(act + (size_t)b * 3 * NPTS);
    float4* sp4 = (float4*)sp;
    float4* sq4 = (float4*)sq;

    float4 pa = p4[3 * tid + 0], pb = p4[3 * tid + 1], pc = p4[3 * tid + 2];
    float4 qa = q4[3 * tid + 0], qb = q4[3 * tid + 1], qc = q4[3 * tid + 2];
    sp4[3 * tid + 0] = pa; sp4[3 * tid + 1] = pb; sp4[3 * tid + 2] = pc;
    sq4[3 * tid + 0] = qa; sq4[3 * tid + 1] = qb; sq4[3 * tid + 2] = qc;

    float px[PPT] = {pa.x, pa.w, pb.z, pc.y};
    float py[PPT] = {pa.y, pb.x, pb.w, pc.z};
    float pz[PPT] = {pa.z, pb.y, pc.x, pc.w};
    float qx[PPT] = {qa.x, qa.w, qb.z, qc.y};
    float qy[PPT] = {qa.y, qb.x, qb.w, qc.z};
    float qz[PPT] = {qa.z, qb.y, qc.x, qc.w};

    float acc[15];
#pragma unroll
    for (int v = 0; v < 15; v++) acc[v] = 0.f;
#pragma unroll
    for (int k = 0; k < PPT; k++) {
        acc[0] += px[k]; acc[1] += py[k]; acc[2] += pz[k];
        acc[3] += qx[k]; acc[4] += qy[k]; acc[5] += qz[k];
        acc[6] += qx[k] * px[k]; acc[7] += qx[k] * py[k]; acc[8] += qx[k] * pz[k];
        acc[9] += qy[k] * px[k]; acc[10] += qy[k] * py[k]; acc[11] += qy[k] * pz[k];
        acc[12] += qz[k] * px[k]; acc[13] += qz[k] * py[k]; acc[14] += qz[k] * pz[k];
    }
#pragma unroll
    for (int v = 0; v < 15; v++) {
        float r = warp_sum(acc[v]);
        if (lane == 0) red[wid][v] = r;
    }
    __syncthreads();

    // ---- Warp 0: cross-warp totals lane-parallel, then lane 0 solves ----
    if (wid == 0) {
        float t = 0.f;
        if (lane < 15) {
#pragma unroll
            for (int w = 0; w < TPB / 32; w++) t += red[w][lane];
        }
        float tot[15];
#pragma unroll
        for (int v = 0; v < 15; v++) tot[v] = __shfl_sync(0xffffffffu, t, v);

        if (lane == 0) {
            const float inv_n = 1.0f / (float)NPTS;
            float mup[3] = {tot[0] * inv_n, tot[1] * inv_n, tot[2] * inv_n};
            float muq[3] = {tot[3] * inv_n, tot[4] * inv_n, tot[5] * inv_n};

            float M[3][3];
#pragma unroll
            for (int i = 0; i < 3; i++)
#pragma unroll
                for (int j = 0; j < 3; j++)
                    M[i][j] = tot[6 + 3 * i + j] - (float)NPTS * muq[i] * mup[j];

            float sc = 1e-30f;
#pragma unroll
            for (int i = 0; i < 3; i++)
#pragma unroll
                for (int j = 0; j < 3; j++) sc = fmaxf(sc, fabsf(M[i][j]));
            float invsc = __fdividef(1.0f, sc);
            float a[3][3];
#pragma unroll
            for (int i = 0; i < 3; i++)
#pragma unroll
                for (int j = 0; j < 3; j++) a[i][j] = M[i][j] * invsc;

            // B = a^T a (symmetric, eigenvalues in [0, 3])
            float B[3][3];
#pragma unroll
            for (int i = 0; i < 3; i++)
#pragma unroll
                for (int j = i; j < 3; j++) {
                    float s = 0.f;
#pragma unroll
                    for (int k = 0; k < 3; k++) s += a[k][i] * a[k][j];
                    B[i][j] = s; B[j][i] = s;
                }

            // Analytic eigenvalues (trigonometric form)
            float qm = (B[0][0] + B[1][1] + B[2][2]) * (1.0f / 3.0f);
            float b00 = B[0][0] - qm, b11 = B[1][1] - qm, b22 = B[2][2] - qm;
            float p1 = B[0][1] * B[0][1] + B[0][2] * B[0][2] + B[1][2] * B[1][2];
            float p2 = b00 * b00 + b11 * b11 + b22 * b22 + 2.0f * p1;
            float pp = sqrtf(p2 * (1.0f / 6.0f) + 1e-30f);
            float invp = __fdividef(1.0f, pp);
            float c00 = b00 * invp, c11 = b11 * invp, c22 = b22 * invp;
            float c01 = B[0][1] * invp, c02 = B[0][2] * invp, c12 = B[1][2] * invp;
            float detC = c00 * (c11 * c22 - c12 * c12)
                       - c01 * (c01 * c22 - c12 * c02)
                       + c02 * (c01 * c12 - c11 * c02);
            float r = fminf(fmaxf(0.5f * detC, -1.0f), 1.0f);
            float phi = acosf(r) * (1.0f / 3.0f);
            float lam0 = qm + 2.0f * pp * cosf(phi);                  // largest
            float lam2 = qm + 2.0f * pp * cosf(phi + 2.0943951024f);  // smallest
            float lam1 = 3.0f * qm - lam0 - lam2;

            // Eigenvectors: extremes via cross-products, middle via cross
            float v0[3], v2[3], v1[3];
            eigvec3(B, lam0, v0);
            eigvec3(B, lam2, v2);
            v1[0] = v2[1] * v0[2] - v2[2] * v0[1];
            v1[1] = v2[2] * v0[0] - v2[0] * v0[2];
            v1[2] = v2[0] * v0[1] - v2[1] * v0[0];
            float n1 = v1[0] * v1[0] + v1[1] * v1[1] + v1[2] * v1[2];
            float in1 = rsqrtf(fmaxf(n1, 1e-30f));
            v1[0] *= in1; v1[1] *= in1; v1[2] *= in1;

            float det = a[0][0] * (a[1][1] * a[2][2] - a[1][2] * a[2][1]) -
                        a[0][1] * (a[1][0] * a[2][2] - a[1][2] * a[2][0]) +
                        a[0][2] * (a[1][0] * a[2][1] - a[1][1] * a[2][0]);
            float dsgn = (det >= 0.f) ? 1.f : -1.f;

            float cv0 = rsqrtf(fmaxf(lam0, 1e-20f));
            float cv1 = rsqrtf(fmaxf(lam1, 1e-20f));
            float cv2 = dsgn * rsqrtf(fmaxf(lam2, 1e-20f));

            // G = cv0 v0 v0^T + cv1 v1 v1^T + cv2 v2 v2^T ; R = a G
            float G[3][3];
#pragma unroll
            for (int i = 0; i < 3; i++)
#pragma unroll
                for (int j = 0; j < 3; j++)
                    G[i][j] = cv0 * v0[i] * v0[j] + cv1 * v1[i] * v1[j] + cv2 * v2[i] * v2[j];
#pragma unroll
            for (int i = 0; i < 3; i++)
#pragma unroll
                for (int j = 0; j < 3; j++) {
                    float s = 0.f;
#pragma unroll
                    for (int k = 0; k < 3; k++) s += a[i][k] * G[k][j];
                    sRm[3 * i + j] = s;
                }
            sRm[9] = mup[0];  sRm[10] = mup[1]; sRm[11] = mup[2];
            sRm[12] = muq[0]; sRm[13] = muq[1]; sRm[14] = muq[2];
        }
    }
    __syncthreads();

    // ---- Phase 2: per-residue deviation + TM term from SMEM ----
    const float R00 = sRm[0], R01 = sRm[1], R02 = sRm[2];
    const float R10 = sRm[3], R11 = sRm[4], R12 = sRm[5];
    const float R20 = sRm[6], R21 = sRm[7], R22 = sRm[8];
    const float mup0 = sRm[9], mup1 = sRm[10], mup2 = sRm[11];
    const float muq0 = sRm[12], muq1 = sRm[13], muq2 = sRm[14];
    const float EPS = 1e-8f;

    float4 ra = sp4[3 * tid + 0], rb = sp4[3 * tid + 1], rc = sp4[3 * tid + 2];
    float4 sa = sq4[3 * tid + 0], sb = sq4[3 * tid + 1], scq = sq4[3 * tid + 2];
    float ppx[PPT] = {ra.x, ra.w, rb.z, rc.y};
    float ppy[PPT] = {ra.y, rb.x, rb.w, rc.z};
    float ppz[PPT] = {ra.z, rb.y, rc.x, rc.w};
    float qqx[PPT] = {sa.x, sa.w, sb.z, scq.y};
    float qqy[PPT] = {sa.y, sb.x, sb.w, scq.z};
    float qqz[PPT] = {sa.z, sb.y, scq.x, scq.w};

    float fsum = 0.f;
#pragma unroll
    for (int k = 0; k < PPT; k++) {
        float cx = qqx[k] - muq0;
        float cy = qqy[k] - muq1;
        float cz = qqz[k] - muq2;
        float ax = cx * R00 + cy * R10 + cz * R20;
        float ay = cx * R01 + cy * R11 + cz * R21;
        float az = cx * R02 + cy * R12 + cz * R22;
        float dx = (ppx[k] - mup0) - ax + EPS;
        float dy = (ppy[k] - mup1) - ay + EPS;
        float dz = (ppz[k] - mup2) - az + EPS;
        float d2 = dx * dx + dy * dy + dz * dz;
        fsum += d0sq / (d0sq + d2);
    }
    fsum = warp_sum(fsum);
    if (lane == 0) red[wid][0] = fsum;
    __syncthreads();

    // ---- Per-batch partial + fused deterministic final reduction ----
    if (tid == 0) {
        float t = 0.f;
#pragma unroll
        for (int w = 0; w < TPB / 32; w++) t += red[w][0];
        g_partial[b] = t;
        __threadfence();
        unsigned r = atomicAdd(&g_count, 1u);
        s_last = (r == gridDim.x - 1) ? 1 : 0;
    }
    __syncthreads();

    if (s_last) {
        const int nb = gridDim.x;
        float v = 0.f;
        for (int i = tid; i < nb; i += TPB) v += __ldcg(&g_partial[i]);
        v = warp_sum(v);
        if (lane == 0) red[wid][1] = v;
        __syncthreads();
        if (tid == 0) {
            float t = 0.f;
#pragma unroll
            for (int w = 0; w < TPB / 32; w++) t += red[w][1];
            out[0] = -t * scale;
            g_count = 0;  // reset for replay determinism
        }
    }
}

extern "C" void kernel_launch(void* const* d_in, const int* in_sizes, int n_in,
                              void* d_out, int out_size) {
    const float* pred = (const float*)d_in[0];
    const float* act = (const float*)d_in[1];
    float* out = (float*)d_out;

    int b = in_sizes[0] / (3 * NPTS);
    if (b > MAXB) b = MAXB;

    double d0 = 1.24 * cbrt((double)NPTS - 15.0) - 1.8;
    float d0sq = (float)(d0 * d0);
    float scale = 1.0f / ((float)b * (float)NPTS);

    tm_kernel<<<b, TPB>>>(pred, act, d0sq, out, scale);
}